// round 1
// baseline (speedup 1.0000x reference)
#include <cuda_runtime.h>

#define Nn 40000
#define Mm 10000
#define NNZv 400000
#define FT 128
#define HID 256
#define NCLS 10
#define NG 128
#define BN_EPS 1e-5f

// ---------------- scratch (no allocs allowed) ----------------
__device__ float g_E[(size_t)Mm * HID];      // edge accumulator [M,256]
__device__ float g_P[(size_t)Nn * HID];      // node accumulator [N,256]
__device__ float g_Z[(size_t)Nn * HID];      // MLP intermediate
__device__ float g_h0[(size_t)Nn * HID];     // hidden layer 0
__device__ float g_h1[(size_t)Nn * HID];     // hidden layer 1
__device__ float g_p0[(size_t)Nn * HID];     // pooled hidden 0
__device__ float g_p1[(size_t)Nn * HID];     // pooled hidden 1
__device__ float g_esz[Mm];                  // edge sizes
__device__ float g_dinv[Nn];                 // 1 / rowsum(H H^T)
__device__ float g_stats[2 * HID];           // BN sum / sumsq
__device__ float g_out[(size_t)Nn * NCLS];   // head output per node
__device__ float g_segsum[NG * NCLS];
__device__ float g_segcnt[NG];

// ---------------- kernels ----------------
__global__ void k_zero4(float4* p, int n4) {
    int i = blockIdx.x * blockDim.x + threadIdx.x;
    int stride = gridDim.x * blockDim.x;
    for (; i < n4; i += stride) p[i] = make_float4(0.f, 0.f, 0.f, 0.f);
}

__global__ void k_count(const int* __restrict__ eidx, float* __restrict__ esz) {
    int i = blockIdx.x * blockDim.x + threadIdx.x;
    if (i < NNZv) atomicAdd(&esz[eidx[i]], 1.f);
}

__global__ void k_rowsum(const int* __restrict__ nidx, const int* __restrict__ eidx,
                         const float* __restrict__ esz, float* __restrict__ prow) {
    int i = blockIdx.x * blockDim.x + threadIdx.x;
    if (i < NNZv) atomicAdd(&prow[nidx[i]], esz[eidx[i]]);
}

__global__ void k_dinv(float* d) {
    int i = blockIdx.x * blockDim.x + threadIdx.x;
    if (i < Nn) {
        float v = d[i];
        d[i] = (v > 0.f) ? 1.f / v : 1.f;
    }
}

// one thread per (nnz, 4-channel chunk): gather float4 from src row, atomic-scatter into dst row
template <int LOGC>  // LOGC = log2(D/4); D=128 -> 5, D=256 -> 6
__global__ void k_scatter(const float4* __restrict__ src, const int* __restrict__ sidx,
                          float* __restrict__ dst, const int* __restrict__ didx) {
    const int C = 1 << LOGC;
    int t = blockIdx.x * blockDim.x + threadIdx.x;
    if (t >= (NNZv << LOGC)) return;
    int i = t >> LOGC;
    int c = t & (C - 1);
    int sr = __ldg(&sidx[i]);
    int dr = __ldg(&didx[i]);
    float4 v = __ldg(&src[(size_t)sr * C + c]);
    float* o = dst + ((size_t)dr * C + c) * 4;
    atomicAdd(o + 0, v.x);
    atomicAdd(o + 1, v.y);
    atomicAdd(o + 2, v.z);
    atomicAdd(o + 3, v.w);
}

// C[64x64 tile] = A[row-major MxK] @ B[row-major KxNc] + bias; M,Nc multiples of 64, K of 16
__global__ void k_gemm_bias(const float* __restrict__ A, const float* __restrict__ B,
                            const float* __restrict__ bias, float* __restrict__ C,
                            int K, int Nc) {
    __shared__ float As[16][65];
    __shared__ float Bs[16][64];
    const int t = threadIdx.x;
    const int tx = t & 15, ty = t >> 4;
    const int row0 = blockIdx.y * 64, col0 = blockIdx.x * 64;
    const int lr = t >> 2;          // 0..63 (A row in tile)
    const int lk = (t & 3) << 2;    // 0,4,8,12 (A k offset)
    const int bk = t >> 4;          // 0..15 (B k in tile)
    const int bc = (t & 15) << 2;   // B col*4

    float acc[4][4] = {};
    for (int kb = 0; kb < K; kb += 16) {
        float4 av = *(const float4*)(A + (size_t)(row0 + lr) * K + kb + lk);
        As[lk + 0][lr] = av.x;
        As[lk + 1][lr] = av.y;
        As[lk + 2][lr] = av.z;
        As[lk + 3][lr] = av.w;
        float4 bv = *(const float4*)(B + (size_t)(kb + bk) * Nc + col0 + bc);
        *(float4*)&Bs[bk][bc] = bv;
        __syncthreads();
#pragma unroll
        for (int k = 0; k < 16; k++) {
            float a[4], b[4];
#pragma unroll
            for (int i = 0; i < 4; i++) a[i] = As[k][ty * 4 + i];
#pragma unroll
            for (int j = 0; j < 4; j++) b[j] = Bs[k][tx * 4 + j];
#pragma unroll
            for (int i = 0; i < 4; i++)
#pragma unroll
                for (int j = 0; j < 4; j++) acc[i][j] += a[i] * b[j];
        }
        __syncthreads();
    }
#pragma unroll
    for (int i = 0; i < 4; i++) {
        float* crow = C + (size_t)(row0 + ty * 4 + i) * Nc + col0 + tx * 4;
#pragma unroll
        for (int j = 0; j < 4; j++) crow[j] = acc[i][j] + bias[col0 + tx * 4 + j];
    }
}

#define BN_ROWS 50
__global__ void k_bnstats(const float* __restrict__ x, float* __restrict__ stats) {
    int c = threadIdx.x;  // 256 threads = 256 channels
    int r0 = blockIdx.x * BN_ROWS;
    float s = 0.f, q = 0.f;
#pragma unroll 5
    for (int r = 0; r < BN_ROWS; r++) {
        float v = x[(size_t)(r0 + r) * HID + c];
        s += v;
        q += v * v;
    }
    atomicAdd(&stats[c], s);
    atomicAdd(&stats[HID + c], q);
}

__global__ void k_bnrelu(float* __restrict__ x, const float* __restrict__ stats,
                         const float* __restrict__ g, const float* __restrict__ b) {
    int t = blockIdx.x * blockDim.x + threadIdx.x;
    if (t >= Nn * HID / 4) return;
    int c4 = (t & (HID / 4 - 1)) * 4;
    float4 v = ((float4*)x)[t];
    float* pv = &v.x;
#pragma unroll
    for (int j = 0; j < 4; j++) {
        int c = c4 + j;
        float mean = stats[c] * (1.f / Nn);
        float var = stats[HID + c] * (1.f / Nn) - mean * mean;
        float sc = g[c] * rsqrtf(var + BN_EPS);
        float y = (pv[j] - mean) * sc + b[c];
        pv[j] = fmaxf(y, 0.f);
    }
    ((float4*)x)[t] = v;
}

__global__ void k_dscale(float* __restrict__ x, const float* __restrict__ dinv) {
    int t = blockIdx.x * blockDim.x + threadIdx.x;
    if (t >= Nn * HID / 4) return;
    int n = t >> 6;  // HID/4 = 64
    float s = dinv[n];
    float4 v = ((float4*)x)[t];
    v.x *= s; v.y *= s; v.z *= s; v.w *= s;
    ((float4*)x)[t] = v;
}

// one warp per node: out[n] = [p0[n] | p1[n]] @ W + hb
__global__ void k_head(const float* __restrict__ p0, const float* __restrict__ p1,
                       const float* __restrict__ W, const float* __restrict__ hb,
                       float* __restrict__ out) {
    int wid = (blockIdx.x * blockDim.x + threadIdx.x) >> 5;
    int lane = threadIdx.x & 31;
    if (wid >= Nn) return;
    float acc[NCLS] = {};
    const float* r0 = p0 + (size_t)wid * HID;
    const float* r1 = p1 + (size_t)wid * HID;
    for (int k = lane; k < HID; k += 32) {
        float v = r0[k];
        const float* w = W + (size_t)k * NCLS;
#pragma unroll
        for (int c = 0; c < NCLS; c++) acc[c] += v * w[c];
        float v2 = r1[k];
        const float* w2 = W + (size_t)(HID + k) * NCLS;
#pragma unroll
        for (int c = 0; c < NCLS; c++) acc[c] += v2 * w2[c];
    }
#pragma unroll
    for (int o = 16; o > 0; o >>= 1)
#pragma unroll
        for (int c = 0; c < NCLS; c++) acc[c] += __shfl_down_sync(0xffffffffu, acc[c], o);
    if (lane == 0) {
#pragma unroll
        for (int c = 0; c < NCLS; c++) out[(size_t)wid * NCLS + c] = acc[c] + hb[c];
    }
}

__global__ void k_seg(const float* __restrict__ out, const int* __restrict__ batch,
                      float* __restrict__ ssum, float* __restrict__ scnt) {
    int n = blockIdx.x * blockDim.x + threadIdx.x;
    if (n >= Nn) return;
    int b = batch[n];
    atomicAdd(&scnt[b], 1.f);
#pragma unroll
    for (int c = 0; c < NCLS; c++) atomicAdd(&ssum[b * NCLS + c], out[(size_t)n * NCLS + c]);
}

__global__ void k_fin(const float* __restrict__ ssum, const float* __restrict__ scnt,
                      float* __restrict__ dout) {
    int t = blockIdx.x * blockDim.x + threadIdx.x;
    if (t < NG * NCLS) {
        int gidx = t / NCLS;
        dout[t] = ssum[t] / fmaxf(scnt[gidx], 1.f);
    }
}

// ---------------- host ----------------
static inline void zero4(float* p, size_t n) {
    int n4 = (int)(n / 4);
    int blocks = (n4 + 255) / 256;
    if (blocks > 4096) blocks = 4096;
    k_zero4<<<blocks, 256>>>((float4*)p, n4);
}

extern "C" void kernel_launch(void* const* d_in, const int* in_sizes, int n_in,
                              void* d_out, int out_size) {
    const float* X = (const float*)d_in[0];
    const int* node_idx = (const int*)d_in[1];
    const int* edge_idx = (const int*)d_in[2];
    const int* all_batch = (const int*)d_in[3];
    const float* W1_0 = (const float*)d_in[4];
    const float* b1_0 = (const float*)d_in[5];
    const float* g1_0 = (const float*)d_in[6];
    const float* be1_0 = (const float*)d_in[7];
    const float* W2_0 = (const float*)d_in[8];
    const float* b2_0 = (const float*)d_in[9];
    const float* bng_0 = (const float*)d_in[10];
    const float* bnb_0 = (const float*)d_in[11];
    const float* W1_1 = (const float*)d_in[12];
    const float* b1_1 = (const float*)d_in[13];
    const float* g1_1 = (const float*)d_in[14];
    const float* be1_1 = (const float*)d_in[15];
    const float* W2_1 = (const float*)d_in[16];
    const float* b2_1 = (const float*)d_in[17];
    const float* bng_1 = (const float*)d_in[18];
    const float* bnb_1 = (const float*)d_in[19];
    const float* head_W = (const float*)d_in[20];
    const float* head_b = (const float*)d_in[21];

    float *E, *P, *Z, *h0, *h1, *p0, *p1, *esz, *dinv, *stats, *outp, *ssum, *scnt;
    cudaGetSymbolAddress((void**)&E, g_E);
    cudaGetSymbolAddress((void**)&P, g_P);
    cudaGetSymbolAddress((void**)&Z, g_Z);
    cudaGetSymbolAddress((void**)&h0, g_h0);
    cudaGetSymbolAddress((void**)&h1, g_h1);
    cudaGetSymbolAddress((void**)&p0, g_p0);
    cudaGetSymbolAddress((void**)&p1, g_p1);
    cudaGetSymbolAddress((void**)&esz, g_esz);
    cudaGetSymbolAddress((void**)&dinv, g_dinv);
    cudaGetSymbolAddress((void**)&stats, g_stats);
    cudaGetSymbolAddress((void**)&outp, g_out);
    cudaGetSymbolAddress((void**)&ssum, g_segsum);
    cudaGetSymbolAddress((void**)&scnt, g_segcnt);

    const int SB = 256;
    const int nnz_blocks = (NNZv + SB - 1) / SB;
    const int sc5_blocks = ((NNZv << 5) + SB - 1) / SB;
    const int sc6_blocks = ((NNZv << 6) + SB - 1) / SB;
    const int elem4_blocks = (Nn * HID / 4 + SB - 1) / SB;

    // ---- degree precompute ----
    zero4(esz, Mm);
    zero4(dinv, Nn);
    k_count<<<nnz_blocks, SB>>>(edge_idx, esz);
    k_rowsum<<<nnz_blocks, SB>>>(node_idx, edge_idx, esz, dinv);
    k_dinv<<<(Nn + SB - 1) / SB, SB>>>(dinv);

    // ---- layer 0 : h0 = relu(BN( relu(BN(HHt(X) @ W1)) @ W2 )) ----
    zero4(E, (size_t)Mm * FT);
    k_scatter<5><<<sc5_blocks, SB>>>((const float4*)X, node_idx, E, edge_idx);
    zero4(P, (size_t)Nn * FT);
    k_scatter<5><<<sc5_blocks, SB>>>((const float4*)E, edge_idx, P, node_idx);
    k_gemm_bias<<<dim3(HID / 64, Nn / 64), 256>>>(P, W1_0, b1_0, Z, FT, HID);
    zero4(stats, 2 * HID);
    k_bnstats<<<Nn / BN_ROWS, HID>>>(Z, stats);
    k_bnrelu<<<elem4_blocks, SB>>>(Z, stats, g1_0, be1_0);
    k_gemm_bias<<<dim3(HID / 64, Nn / 64), 256>>>(Z, W2_0, b2_0, h0, HID, HID);
    zero4(stats, 2 * HID);
    k_bnstats<<<Nn / BN_ROWS, HID>>>(h0, stats);
    k_bnrelu<<<elem4_blocks, SB>>>(h0, stats, bng_0, bnb_0);

    // ---- layer 1 ----
    zero4(E, (size_t)Mm * HID);
    k_scatter<6><<<sc6_blocks, SB>>>((const float4*)h0, node_idx, E, edge_idx);
    zero4(P, (size_t)Nn * HID);
    k_scatter<6><<<sc6_blocks, SB>>>((const float4*)E, edge_idx, P, node_idx);
    k_gemm_bias<<<dim3(HID / 64, Nn / 64), 256>>>(P, W1_1, b1_1, Z, HID, HID);
    zero4(stats, 2 * HID);
    k_bnstats<<<Nn / BN_ROWS, HID>>>(Z, stats);
    k_bnrelu<<<elem4_blocks, SB>>>(Z, stats, g1_1, be1_1);
    k_gemm_bias<<<dim3(HID / 64, Nn / 64), 256>>>(Z, W2_1, b2_1, h1, HID, HID);
    zero4(stats, 2 * HID);
    k_bnstats<<<Nn / BN_ROWS, HID>>>(h1, stats);
    k_bnrelu<<<elem4_blocks, SB>>>(h1, stats, bng_1, bnb_1);

    // ---- pooling: p_i = d_inv * H(Ht(h_i)) ----
    zero4(E, (size_t)Mm * HID);
    k_scatter<6><<<sc6_blocks, SB>>>((const float4*)h0, node_idx, E, edge_idx);
    zero4(p0, (size_t)Nn * HID);
    k_scatter<6><<<sc6_blocks, SB>>>((const float4*)E, edge_idx, p0, node_idx);
    k_dscale<<<elem4_blocks, SB>>>(p0, dinv);

    zero4(E, (size_t)Mm * HID);
    k_scatter<6><<<sc6_blocks, SB>>>((const float4*)h1, node_idx, E, edge_idx);
    zero4(p1, (size_t)Nn * HID);
    k_scatter<6><<<sc6_blocks, SB>>>((const float4*)E, edge_idx, p1, node_idx);
    k_dscale<<<elem4_blocks, SB>>>(p1, dinv);

    // ---- head + per-graph mean readout ----
    k_head<<<(Nn * 32 + SB - 1) / SB, SB>>>(p0, p1, head_W, head_b, outp);
    zero4(ssum, NG * NCLS);
    zero4(scnt, NG);
    k_seg<<<(Nn + SB - 1) / SB, SB>>>(outp, all_batch, ssum, scnt);
    k_fin<<<(NG * NCLS + SB - 1) / SB, SB>>>(ssum, scnt, (float*)d_out);
}

// round 2
// speedup vs baseline: 2.6179x; 2.6179x over previous
#include <cuda_runtime.h>

#define Nn 40000
#define Mm 10000
#define NNZv 400000
#define FT 128
#define HID 256
#define NCLS 10
#define NG 128
#define BN_EPS 1e-5f

// ---------------- scratch (no allocs allowed) ----------------
__device__ float g_E[(size_t)Mm * HID];       // edge accumulator [M,256]
__device__ float g_P0[(size_t)Nn * HID];      // H(Ht(h0)) : layer1 input AND pooled h0 (pre-dinv)
__device__ float g_P1[(size_t)Nn * HID];      // H(Ht(h1)) pooled h1 (pre-dinv); also reused as Pa [N,128]
__device__ float g_Z[(size_t)Nn * HID];       // MLP intermediate
__device__ float g_h0[(size_t)Nn * HID];
__device__ float g_h1[(size_t)Nn * HID];
__device__ float g_dinv[Nn];
__device__ float g_stats[2 * HID];
__device__ float g_out[(size_t)Nn * NCLS];
__device__ float g_segsum[NG * NCLS];
__device__ float g_segcnt[NG];
// CSR structures
__device__ int g_ecnt[Mm];
__device__ int g_estart[Mm + 1];
__device__ int g_ecur[Mm];
__device__ int g_elist[NNZv];     // node indices grouped by edge
__device__ int g_ncnt[Nn];
__device__ int g_nstart[Nn + 1];
__device__ int g_ncur[Nn];
__device__ int g_nlist[NNZv];     // edge indices grouped by node

// ---------------- utility kernels ----------------
__global__ void k_zerof(float* p, int n) {
    int i = blockIdx.x * blockDim.x + threadIdx.x;
    int stride = gridDim.x * blockDim.x;
    for (; i < n; i += stride) p[i] = 0.f;
}
__global__ void k_zeroi(int* p, int n) {
    int i = blockIdx.x * blockDim.x + threadIdx.x;
    int stride = gridDim.x * blockDim.x;
    for (; i < n; i += stride) p[i] = 0;
}

// ---------------- CSR build ----------------
__global__ void k_hist(const int* __restrict__ nidx, const int* __restrict__ eidx,
                       int* __restrict__ ecnt, int* __restrict__ ncnt) {
    int i = blockIdx.x * blockDim.x + threadIdx.x;
    if (i < NNZv) {
        atomicAdd(&ecnt[eidx[i]], 1);
        atomicAdd(&ncnt[nidx[i]], 1);
    }
}

// single-block exclusive scan (deterministic); start[n] gets total
__global__ void k_scan(const int* __restrict__ cnt, int* __restrict__ start,
                       int* __restrict__ cursor, int n) {
    __shared__ int buf[1024];
    __shared__ int carry;
    int t = threadIdx.x;
    if (t == 0) carry = 0;
    __syncthreads();
    for (int base = 0; base < n; base += 1024) {
        int v = (base + t < n) ? cnt[base + t] : 0;
        buf[t] = v;
        __syncthreads();
        for (int off = 1; off < 1024; off <<= 1) {
            int x = (t >= off) ? buf[t - off] : 0;
            __syncthreads();
            buf[t] += x;
            __syncthreads();
        }
        int excl = buf[t] - v + carry;
        if (base + t < n) { start[base + t] = excl; cursor[base + t] = excl; }
        __syncthreads();
        if (t == 1023) carry += buf[1023];
        __syncthreads();
    }
    if (t == 0) start[n] = carry;
}

__global__ void k_fill(const int* __restrict__ nidx, const int* __restrict__ eidx,
                       int* __restrict__ ecur, int* __restrict__ elist,
                       int* __restrict__ ncur, int* __restrict__ nlist) {
    int i = blockIdx.x * blockDim.x + threadIdx.x;
    if (i < NNZv) {
        int e = eidx[i], n = nidx[i];
        int p1 = atomicAdd(&ecur[e], 1);
        elist[p1] = n;
        int p2 = atomicAdd(&ncur[n], 1);
        nlist[p2] = e;
    }
}

__global__ void k_dinv(const int* __restrict__ nstart, const int* __restrict__ nlist,
                       const int* __restrict__ estart, float* __restrict__ dinv) {
    int n = blockIdx.x * blockDim.x + threadIdx.x;
    if (n >= Nn) return;
    int s = nstart[n], e = nstart[n + 1];
    float sum = 0.f;
    for (int j = s; j < e; j++) {
        int ed = nlist[j];
        sum += (float)(estart[ed + 1] - estart[ed]);
    }
    dinv[n] = (sum > 0.f) ? 1.f / sum : 1.f;
}

// ---------------- CSR segment-sum gather: dst[row] = sum src[list[j]] ----------------
// one warp covers 128 channels (32 float4 lanes); D/128 warps per row
template <int D>
__global__ void k_gather(const float4* __restrict__ src, const int* __restrict__ start,
                         const int* __restrict__ list, float4* __restrict__ dst, int rows) {
    constexpr int WPR = D / 128;
    int gw = (blockIdx.x * blockDim.x + threadIdx.x) >> 5;
    int lane = threadIdx.x & 31;
    int row = gw / WPR;
    if (row >= rows) return;
    int col = (gw % WPR) * 32 + lane;   // float4 column, D/4 per row
    int s = __ldg(&start[row]), e = __ldg(&start[row + 1]);
    float4 acc = make_float4(0.f, 0.f, 0.f, 0.f);
    for (int j0 = s; j0 < e; j0 += 32) {
        int cnt = min(32, e - j0);
        int id = 0;
        if (lane < cnt) id = __ldg(&list[j0 + lane]);
        for (int jj = 0; jj < cnt; jj++) {
            int r = __shfl_sync(0xffffffffu, id, jj);
            float4 v = __ldg(&src[(size_t)r * (D / 4) + col]);
            acc.x += v.x; acc.y += v.y; acc.z += v.z; acc.w += v.w;
        }
    }
    dst[(size_t)row * (D / 4) + col] = acc;
}

// ---------------- GEMM: C = A[M x K] @ B[K x Nc] + bias ----------------
// 64x64 tile, 128 threads, 8x4 accum per thread (FMA-bound: 3 LDS.128 vs 32 FFMA per k)
__global__ __launch_bounds__(128) void k_gemm_bias(
    const float* __restrict__ A, const float* __restrict__ B,
    const float* __restrict__ bias, float* __restrict__ C, int K, int Nc) {
    __shared__ float As[16][68];
    __shared__ float Bs[16][64];
    const int t = threadIdx.x;
    const int row0 = blockIdx.y * 64, col0 = blockIdx.x * 64;
    const int tx = t & 15, ty = t >> 4;   // col = col0+tx*4, rows = row0+ty*8..+7

    float acc[8][4] = {};
    for (int kb = 0; kb < K; kb += 16) {
#pragma unroll
        for (int s0 = 0; s0 < 2; s0++) {
            int s = t + s0 * 128;
            int ar = s >> 2, ak = (s & 3) << 2;
            float4 av = *(const float4*)(A + (size_t)(row0 + ar) * K + kb + ak);
            As[ak + 0][ar] = av.x;
            As[ak + 1][ar] = av.y;
            As[ak + 2][ar] = av.z;
            As[ak + 3][ar] = av.w;
            int bk = s >> 4, bc = (s & 15) << 2;
            float4 bv = *(const float4*)(B + (size_t)(kb + bk) * Nc + col0 + bc);
            *(float4*)&Bs[bk][bc] = bv;
        }
        __syncthreads();
#pragma unroll
        for (int k = 0; k < 16; k++) {
            float a[8], b[4];
            *(float4*)&a[0] = *(const float4*)&As[k][ty * 8];
            *(float4*)&a[4] = *(const float4*)&As[k][ty * 8 + 4];
            *(float4*)&b[0] = *(const float4*)&Bs[k][tx * 4];
#pragma unroll
            for (int i = 0; i < 8; i++)
#pragma unroll
                for (int j = 0; j < 4; j++) acc[i][j] += a[i] * b[j];
        }
        __syncthreads();
    }
    float4 bv = *(const float4*)&bias[col0 + tx * 4];
#pragma unroll
    for (int i = 0; i < 8; i++) {
        float4 o;
        o.x = acc[i][0] + bv.x;
        o.y = acc[i][1] + bv.y;
        o.z = acc[i][2] + bv.z;
        o.w = acc[i][3] + bv.w;
        *(float4*)(C + (size_t)(row0 + ty * 8 + i) * Nc + col0 + tx * 4) = o;
    }
}

// ---------------- BatchNorm ----------------
#define BN_ROWS 50
__global__ void k_bnstats(const float* __restrict__ x, float* __restrict__ stats) {
    int c = threadIdx.x;
    int r0 = blockIdx.x * BN_ROWS;
    float s = 0.f, q = 0.f;
#pragma unroll 5
    for (int r = 0; r < BN_ROWS; r++) {
        float v = x[(size_t)(r0 + r) * HID + c];
        s += v;
        q += v * v;
    }
    atomicAdd(&stats[c], s);
    atomicAdd(&stats[HID + c], q);
}

__global__ void k_bnrelu(float* __restrict__ x, const float* __restrict__ stats,
                         const float* __restrict__ g, const float* __restrict__ b) {
    int t = blockIdx.x * blockDim.x + threadIdx.x;
    if (t >= Nn * HID / 4) return;
    int c4 = (t & (HID / 4 - 1)) * 4;
    float4 v = ((float4*)x)[t];
    float* pv = &v.x;
#pragma unroll
    for (int j = 0; j < 4; j++) {
        int c = c4 + j;
        float mean = stats[c] * (1.f / Nn);
        float var = stats[HID + c] * (1.f / Nn) - mean * mean;
        float sc = g[c] * rsqrtf(var + BN_EPS);
        float y = (pv[j] - mean) * sc + b[c];
        pv[j] = fmaxf(y, 0.f);
    }
    ((float4*)x)[t] = v;
}

// ---------------- head: out[n] = dinv[n]*([P0|P1] @ W) + hb ----------------
__global__ void k_head(const float* __restrict__ p0, const float* __restrict__ p1,
                       const float* __restrict__ dinv,
                       const float* __restrict__ W, const float* __restrict__ hb,
                       float* __restrict__ out) {
    int wid = (blockIdx.x * blockDim.x + threadIdx.x) >> 5;
    int lane = threadIdx.x & 31;
    if (wid >= Nn) return;
    float acc[NCLS] = {};
    const float* r0 = p0 + (size_t)wid * HID;
    const float* r1 = p1 + (size_t)wid * HID;
    for (int k = lane; k < HID; k += 32) {
        float v = r0[k];
        const float* w = W + (size_t)k * NCLS;
#pragma unroll
        for (int c = 0; c < NCLS; c++) acc[c] += v * w[c];
        float v2 = r1[k];
        const float* w2 = W + (size_t)(HID + k) * NCLS;
#pragma unroll
        for (int c = 0; c < NCLS; c++) acc[c] += v2 * w2[c];
    }
#pragma unroll
    for (int o = 16; o > 0; o >>= 1)
#pragma unroll
        for (int c = 0; c < NCLS; c++) acc[c] += __shfl_down_sync(0xffffffffu, acc[c], o);
    if (lane == 0) {
        float d = dinv[wid];
#pragma unroll
        for (int c = 0; c < NCLS; c++) out[(size_t)wid * NCLS + c] = acc[c] * d + hb[c];
    }
}

__global__ void k_seg(const float* __restrict__ out, const int* __restrict__ batch,
                      float* __restrict__ ssum, float* __restrict__ scnt) {
    int n = blockIdx.x * blockDim.x + threadIdx.x;
    if (n >= Nn) return;
    int b = batch[n];
    atomicAdd(&scnt[b], 1.f);
#pragma unroll
    for (int c = 0; c < NCLS; c++) atomicAdd(&ssum[b * NCLS + c], out[(size_t)n * NCLS + c]);
}

__global__ void k_fin(const float* __restrict__ ssum, const float* __restrict__ scnt,
                      float* __restrict__ dout) {
    int t = blockIdx.x * blockDim.x + threadIdx.x;
    if (t < NG * NCLS) {
        int gidx = t / NCLS;
        dout[t] = ssum[t] / fmaxf(scnt[gidx], 1.f);
    }
}

// ---------------- host ----------------
extern "C" void kernel_launch(void* const* d_in, const int* in_sizes, int n_in,
                              void* d_out, int out_size) {
    const float* X = (const float*)d_in[0];
    const int* node_idx = (const int*)d_in[1];
    const int* edge_idx = (const int*)d_in[2];
    const int* all_batch = (const int*)d_in[3];
    const float* W1_0 = (const float*)d_in[4];
    const float* b1_0 = (const float*)d_in[5];
    const float* g1_0 = (const float*)d_in[6];
    const float* be1_0 = (const float*)d_in[7];
    const float* W2_0 = (const float*)d_in[8];
    const float* b2_0 = (const float*)d_in[9];
    const float* bng_0 = (const float*)d_in[10];
    const float* bnb_0 = (const float*)d_in[11];
    const float* W1_1 = (const float*)d_in[12];
    const float* b1_1 = (const float*)d_in[13];
    const float* g1_1 = (const float*)d_in[14];
    const float* be1_1 = (const float*)d_in[15];
    const float* W2_1 = (const float*)d_in[16];
    const float* b2_1 = (const float*)d_in[17];
    const float* bng_1 = (const float*)d_in[18];
    const float* bnb_1 = (const float*)d_in[19];
    const float* head_W = (const float*)d_in[20];
    const float* head_b = (const float*)d_in[21];

    float *E, *P0, *P1, *Z, *h0, *h1, *dinv, *stats, *outp, *ssum, *scnt;
    int *ecnt, *estart, *ecur, *elist, *ncnt, *nstart, *ncur, *nlist;
    cudaGetSymbolAddress((void**)&E, g_E);
    cudaGetSymbolAddress((void**)&P0, g_P0);
    cudaGetSymbolAddress((void**)&P1, g_P1);
    cudaGetSymbolAddress((void**)&Z, g_Z);
    cudaGetSymbolAddress((void**)&h0, g_h0);
    cudaGetSymbolAddress((void**)&h1, g_h1);
    cudaGetSymbolAddress((void**)&dinv, g_dinv);
    cudaGetSymbolAddress((void**)&stats, g_stats);
    cudaGetSymbolAddress((void**)&outp, g_out);
    cudaGetSymbolAddress((void**)&ssum, g_segsum);
    cudaGetSymbolAddress((void**)&scnt, g_segcnt);
    cudaGetSymbolAddress((void**)&ecnt, g_ecnt);
    cudaGetSymbolAddress((void**)&estart, g_estart);
    cudaGetSymbolAddress((void**)&ecur, g_ecur);
    cudaGetSymbolAddress((void**)&elist, g_elist);
    cudaGetSymbolAddress((void**)&ncnt, g_ncnt);
    cudaGetSymbolAddress((void**)&nstart, g_nstart);
    cudaGetSymbolAddress((void**)&ncur, g_ncur);
    cudaGetSymbolAddress((void**)&nlist, g_nlist);

    const int SB = 256;
    const int nnz_blocks = (NNZv + SB - 1) / SB;
    const int elem4_blocks = (Nn * HID / 4 + SB - 1) / SB;
    // gather grids: warps = rows * (D/128)
    const int ge128 = (Mm * 32 + SB - 1) / SB;        // edges, D=128
    const int gn128 = (Nn * 32 + SB - 1) / SB;        // nodes, D=128
    const int ge256 = (Mm * 2 * 32 + SB - 1) / SB;    // edges, D=256
    const int gn256 = (Nn * 2 * 32 + SB - 1) / SB;    // nodes, D=256
    dim3 gemm_grid(HID / 64, Nn / 64);

    // ---- CSR build ----
    k_zeroi<<<64, SB>>>(ecnt, Mm);
    k_zeroi<<<64, SB>>>(ncnt, Nn);
    k_hist<<<nnz_blocks, SB>>>(node_idx, edge_idx, ecnt, ncnt);
    k_scan<<<1, 1024>>>(ecnt, estart, ecur, Mm);
    k_scan<<<1, 1024>>>(ncnt, nstart, ncur, Nn);
    k_fill<<<nnz_blocks, SB>>>(node_idx, edge_idx, ecur, elist, ncur, nlist);
    k_dinv<<<(Nn + SB - 1) / SB, SB>>>(nstart, nlist, estart, dinv);

    // ---- layer 0 ----  (Pa stored in P1 buffer, [N,128])
    k_gather<128><<<ge128, SB>>>((const float4*)X, estart, elist, (float4*)E, Mm);
    k_gather<128><<<gn128, SB>>>((const float4*)E, nstart, nlist, (float4*)P1, Nn);
    k_gemm_bias<<<gemm_grid, 128>>>(P1, W1_0, b1_0, Z, FT, HID);
    k_zerof<<<2, SB>>>(stats, 2 * HID);
    k_bnstats<<<Nn / BN_ROWS, HID>>>(Z, stats);
    k_bnrelu<<<elem4_blocks, SB>>>(Z, stats, g1_0, be1_0);
    k_gemm_bias<<<gemm_grid, 128>>>(Z, W2_0, b2_0, h0, HID, HID);
    k_zerof<<<2, SB>>>(stats, 2 * HID);
    k_bnstats<<<Nn / BN_ROWS, HID>>>(h0, stats);
    k_bnrelu<<<elem4_blocks, SB>>>(h0, stats, bng_0, bnb_0);

    // ---- layer 1 ----  (P0 = H(Ht(h0)) kept for head)
    k_gather<256><<<ge256, SB>>>((const float4*)h0, estart, elist, (float4*)E, Mm);
    k_gather<256><<<gn256, SB>>>((const float4*)E, nstart, nlist, (float4*)P0, Nn);
    k_gemm_bias<<<gemm_grid, 128>>>(P0, W1_1, b1_1, Z, HID, HID);
    k_zerof<<<2, SB>>>(stats, 2 * HID);
    k_bnstats<<<Nn / BN_ROWS, HID>>>(Z, stats);
    k_bnrelu<<<elem4_blocks, SB>>>(Z, stats, g1_1, be1_1);
    k_gemm_bias<<<gemm_grid, 128>>>(Z, W2_1, b2_1, h1, HID, HID);
    k_zerof<<<2, SB>>>(stats, 2 * HID);
    k_bnstats<<<Nn / BN_ROWS, HID>>>(h1, stats);
    k_bnrelu<<<elem4_blocks, SB>>>(h1, stats, bng_1, bnb_1);

    // ---- pooling for h1 only (h0's pooled value is P0) ----
    k_gather<256><<<ge256, SB>>>((const float4*)h1, estart, elist, (float4*)E, Mm);
    k_gather<256><<<gn256, SB>>>((const float4*)E, nstart, nlist, (float4*)P1, Nn);

    // ---- head + readout ----
    k_head<<<(Nn * 32 + SB - 1) / SB, SB>>>(P0, P1, dinv, head_W, head_b, outp);
    k_zerof<<<2, SB>>>(ssum, NG * NCLS);
    k_zerof<<<1, SB>>>(scnt, NG);
    k_seg<<<(Nn + SB - 1) / SB, SB>>>(outp, all_batch, ssum, scnt);
    k_fin<<<(NG * NCLS + SB - 1) / SB, SB>>>(ssum, scnt, (float*)d_out);
}